// round 6
// baseline (speedup 1.0000x reference)
#include <cuda_runtime.h>
#include <math_constants.h>
#include <math.h>

#define TOTAL 262144
#define NB 64
#define NA 128
#define MAXV 4608
#define VQ (MAXV/4)          // 1152 float4 per padded row
#define NBA (NB*NA)          // 8192 output rows
#define GEMV_WARPS 65536     // TOTAL/4 rows-per-warp
#define GEMV_BLOCKS 5462     // ceil(65536/12)

// ---- scratch (static __device__ arrays; no allocation allowed) ----
__device__ float g_z[TOTAL];
__device__ float g_coord[NB][3];
__device__ float g_padded[NB * MAXV]; // 1.18 MB, fully written by K2

__device__ __forceinline__ void stcs4(float4* p, float4 v) {
    asm volatile("st.global.cs.v4.f32 [%0], {%1,%2,%3,%4};"
                 :: "l"(p), "f"(v.x), "f"(v.y), "f"(v.z), "f"(v.w) : "memory");
}

// K1 fused: blocks [0, NBA) zero-fill unmasked output rows;
//           blocks [NBA, NBA+GEMV_BLOCKS) do the 4-row/warp GEMV.
__global__ __launch_bounds__(384) void k_gemv_fill(const float* __restrict__ emb,
                                                   const float* __restrict__ Ww,
                                                   const float* __restrict__ bw,
                                                   const int* __restrict__ mask,
                                                   float* __restrict__ out) {
    int t = threadIdx.x;
    if (blockIdx.x < NBA) {
        int ba = blockIdx.x;
        if (__ldg(&mask[ba])) return;               // masked rows written by K3
        float4* out_row = ((float4*)(out + NBA * 3)) + (size_t)ba * VQ;
        float4 z = make_float4(0.0f, 0.0f, 0.0f, 0.0f);
        stcs4(out_row + t, z);
        stcs4(out_row + t + 384, z);
        stcs4(out_row + t + 768, z);
        if (t < 3) out[ba * 3 + t] = 0.0f;
        return;
    }

    // GEMV: 12 warps/block, 4 rows/warp
    int warp = (blockIdx.x - NBA) * 12 + (t >> 5);
    if (warp >= GEMV_WARPS) return;
    int lane = t & 31;
    size_t base = (size_t)warp * 4 * 32;

    const float4* emb4 = (const float4*)emb;
    float4 w = __ldg(((const float4*)Ww) + lane);

    float4 e0 = __ldg(emb4 + base + 0 * 32 + lane);
    float4 e1 = __ldg(emb4 + base + 1 * 32 + lane);
    float4 e2 = __ldg(emb4 + base + 2 * 32 + lane);
    float4 e3 = __ldg(emb4 + base + 3 * 32 + lane);

    float d0 = fmaf(e0.x, w.x, fmaf(e0.y, w.y, fmaf(e0.z, w.z, e0.w * w.w)));
    float d1 = fmaf(e1.x, w.x, fmaf(e1.y, w.y, fmaf(e1.z, w.z, e1.w * w.w)));
    float d2 = fmaf(e2.x, w.x, fmaf(e2.y, w.y, fmaf(e2.z, w.z, e2.w * w.w)));
    float d3 = fmaf(e3.x, w.x, fmaf(e3.y, w.y, fmaf(e3.z, w.z, e3.w * w.w)));

    #pragma unroll
    for (int o = 16; o; o >>= 1) {
        d0 += __shfl_xor_sync(0xffffffffu, d0, o);
        d1 += __shfl_xor_sync(0xffffffffu, d1, o);
        d2 += __shfl_xor_sync(0xffffffffu, d2, o);
        d3 += __shfl_xor_sync(0xffffffffu, d3, o);
    }
    if (lane == 0) {
        float bias = bw[0];
        ((float4*)g_z)[warp] = make_float4(d0 + bias, d1 + bias, d2 + bias, d3 + bias);
    }
}

// K2: one block per batch segment. Binary-search bounds, block-reduce softmax,
// coord accumulation in registers, write full padded row (incl. zero tail).
__global__ __launch_bounds__(1024) void k_segsoftmax(const int* __restrict__ bidx,
                                                     const float* __restrict__ coords) {
    __shared__ float s_z[MAXV];        // 18 KB
    __shared__ float s_red[32];
    __shared__ float s_red4[32][4];
    __shared__ int   s_lo, s_hi;
    __shared__ float s_m, s_denom;

    int b = blockIdx.x;
    int t = threadIdx.x;

    if (t == 0) {
        int lo = 0, hi = TOTAL;
        while (lo < hi) { int mid = (lo + hi) >> 1; if (bidx[mid] < b) lo = mid + 1; else hi = mid; }
        s_lo = lo;
        int lo2 = lo, hi2 = TOTAL;
        while (lo2 < hi2) { int mid = (lo2 + hi2) >> 1; if (bidx[mid] < b + 1) lo2 = mid + 1; else hi2 = mid; }
        s_hi = lo2;
    }
    __syncthreads();
    const int lo = s_lo, cnt = s_hi - s_lo;

    float lmax = -CUDART_INF_F;
    for (int i = t; i < cnt; i += 1024) {
        float v = g_z[lo + i];
        s_z[i] = v;
        lmax = fmaxf(lmax, v);
    }
    #pragma unroll
    for (int o = 16; o; o >>= 1) lmax = fmaxf(lmax, __shfl_xor_sync(0xffffffffu, lmax, o));
    if ((t & 31) == 0) s_red[t >> 5] = lmax;
    __syncthreads();
    if (t < 32) {
        float v = s_red[t];
        #pragma unroll
        for (int o = 16; o; o >>= 1) v = fmaxf(v, __shfl_xor_sync(0xffffffffu, v, o));
        if (t == 0) s_m = isfinite(v) ? v : 0.0f;
    }
    __syncthreads();
    const float m = s_m;

    float lsum = 0.0f, cx = 0.0f, cy = 0.0f, cz = 0.0f;
    for (int i = t; i < cnt; i += 1024) {
        float z = expf(s_z[i] - m);
        s_z[i] = z;
        lsum += z;
        int g = lo + i;
        cx = fmaf(z, coords[3 * g + 0], cx);
        cy = fmaf(z, coords[3 * g + 1], cy);
        cz = fmaf(z, coords[3 * g + 2], cz);
    }
    #pragma unroll
    for (int o = 16; o; o >>= 1) {
        lsum += __shfl_xor_sync(0xffffffffu, lsum, o);
        cx   += __shfl_xor_sync(0xffffffffu, cx, o);
        cy   += __shfl_xor_sync(0xffffffffu, cy, o);
        cz   += __shfl_xor_sync(0xffffffffu, cz, o);
    }
    if ((t & 31) == 0) {
        s_red4[t >> 5][0] = lsum; s_red4[t >> 5][1] = cx;
        s_red4[t >> 5][2] = cy;   s_red4[t >> 5][3] = cz;
    }
    __syncthreads();
    if (t < 32) {
        float a0 = s_red4[t][0], a1 = s_red4[t][1], a2 = s_red4[t][2], a3 = s_red4[t][3];
        #pragma unroll
        for (int o = 16; o; o >>= 1) {
            a0 += __shfl_xor_sync(0xffffffffu, a0, o);
            a1 += __shfl_xor_sync(0xffffffffu, a1, o);
            a2 += __shfl_xor_sync(0xffffffffu, a2, o);
            a3 += __shfl_xor_sync(0xffffffffu, a3, o);
        }
        if (t == 0) {
            float denom = (a0 > 0.0f) ? a0 : 1.0f;
            s_denom = denom;
            g_coord[b][0] = a1 / denom;
            g_coord[b][1] = a2 / denom;
            g_coord[b][2] = a3 / denom;
        }
    }
    __syncthreads();
    const float inv = 1.0f / s_denom;

    for (int v = t; v < MAXV; v += 1024)
        g_padded[b * MAXV + v] = (v < cnt) ? s_z[v] * inv : 0.0f;
}

// K3: masked rows only — copy padded row + coords (streaming stores).
__global__ __launch_bounds__(384) void k_output_masked(const int* __restrict__ mask,
                                                       float* __restrict__ out) {
    int ba = blockIdx.x;
    if (!__ldg(&mask[ba])) return;                   // zero rows done in K1
    int b = ba >> 7;
    int t = threadIdx.x;

    float4* out_row = ((float4*)(out + NBA * 3)) + (size_t)ba * VQ;
    const float4* pad_row = ((const float4*)g_padded) + b * VQ;

    float4 v0 = __ldg(pad_row + t);
    float4 v1 = __ldg(pad_row + t + 384);
    float4 v2 = __ldg(pad_row + t + 768);
    stcs4(out_row + t,       v0);
    stcs4(out_row + t + 384, v1);
    stcs4(out_row + t + 768, v2);
    if (t < 3) out[ba * 3 + t] = g_coord[b][t];
}

extern "C" void kernel_launch(void* const* d_in, const int* in_sizes, int n_in,
                              void* d_out, int out_size) {
    const float* emb    = (const float*)d_in[0];   // [TOTAL, 128] f32
    const float* coords = (const float*)d_in[1];   // [TOTAL, 3]   f32
    const int*   mask   = (const int*)d_in[2];     // [64, 128] bool -> int32
    const int*   bidx   = (const int*)d_in[3];     // [TOTAL] sorted, int32
    const float* Ww     = (const float*)d_in[4];   // [1, 128] f32
    const float* bw     = (const float*)d_in[5];   // [1] f32
    float* out = (float*)d_out;

    // K1 fused: 8192 fill blocks + 5462 GEMV blocks
    k_gemv_fill<<<NBA + GEMV_BLOCKS, 384>>>(emb, Ww, bw, mask, out);

    // K2: one block per batch
    k_segsoftmax<<<NB, 1024>>>(bidx, coords);

    // K3: masked rows only
    k_output_masked<<<NBA, 384>>>(mask, out);
}